// round 11
// baseline (speedup 1.0000x reference)
#include <cuda_runtime.h>
#include <cuda_fp16.h>
#include <cstdint>

#define NEG_SLOPE 0.2f

static constexpr int Bb = 8;
static constexpr int Nn = 2048;
static constexpr int Dd = 128;

// Scratch (device globals; allocation-free rule)
__device__ __half g_hh[Bb * Nn * Dd];    // h fp16 (GEMM B operand)
__device__ float  g_e1s[Bb * Nn];        // exp(s_src)
__device__ float  g_e2s[Bb * Nn];        // exp(0.2*s_src)
__device__ float  g_e1d[Bb * Nn];        // exp(s_dst)
__device__ float  g_e2d[Bb * Nn];        // exp(0.2*s_dst)
__device__ float  g_thr[Bb * Nn];        // exp(-s_src)  (cond: e1d_j > thr_i)
__device__ float  g_invd[Bb * Nn];

__device__ __forceinline__ uint32_t f2tf(float x) {
    uint32_t r;
    asm("cvt.rna.tf32.f32 %0, %1;" : "=r"(r) : "f"(x));
    return r;
}
__device__ __forceinline__ float lrelu(float v) { return v > 0.f ? v : NEG_SLOPE * v; }

__device__ __forceinline__ void mma8(float* d, const uint32_t* a, const uint32_t* b) {
    asm volatile(
        "mma.sync.aligned.m16n8k8.row.col.f32.tf32.tf32.f32 "
        "{%0,%1,%2,%3},{%4,%5,%6,%7},{%8,%9},{%0,%1,%2,%3};\n"
        : "+f"(d[0]), "+f"(d[1]), "+f"(d[2]), "+f"(d[3])
        : "r"(a[0]), "r"(a[1]), "r"(a[2]), "r"(a[3]), "r"(b[0]), "r"(b[1]));
}
__device__ __forceinline__ void mma16(float* d, const uint32_t* a, uint32_t b0, uint32_t b1) {
    asm volatile(
        "mma.sync.aligned.m16n8k16.row.col.f32.f16.f16.f32 "
        "{%0,%1,%2,%3},{%4,%5,%6,%7},{%8,%9},{%0,%1,%2,%3};\n"
        : "+f"(d[0]), "+f"(d[1]), "+f"(d[2]), "+f"(d[3])
        : "r"(a[0]), "r"(a[1]), "r"(a[2]), "r"(a[3]), "r"(b0), "r"(b1));
}
__device__ __forceinline__ void ldsm4(uint32_t* r, uint32_t a) {
    asm volatile("ldmatrix.sync.aligned.m8n8.x4.shared.b16 {%0,%1,%2,%3}, [%4];"
                 : "=r"(r[0]), "=r"(r[1]), "=r"(r[2]), "=r"(r[3]) : "r"(a));
}
__device__ __forceinline__ void ldsm4t(uint32_t* r, uint32_t a) {
    asm volatile("ldmatrix.sync.aligned.m8n8.x4.trans.shared.b16 {%0,%1,%2,%3}, [%4];"
                 : "=r"(r[0]), "=r"(r[1]), "=r"(r[2]), "=r"(r[3]) : "r"(a));
}
__device__ __forceinline__ void cp16(void* s, const void* g) {
    uint32_t sa = (uint32_t)__cvta_generic_to_shared(s);
    asm volatile("cp.async.cg.shared.global [%0], [%1], 16;" :: "r"(sa), "l"(g));
}
__device__ __forceinline__ void cp_commit() { asm volatile("cp.async.commit_group;"); }
__device__ __forceinline__ void bar_sync(int id, int cnt) {
    asm volatile("bar.sync %0, %1;" :: "r"(id), "r"(cnt) : "memory");
}
__device__ __forceinline__ void bar_arrive(int id, int cnt) {
    asm volatile("bar.arrive %0, %1;" :: "r"(id), "r"(cnt) : "memory");
}

// ---------------------------------------------------------------------------
// K1: h = x @ W (tf32 mma.sync). Stores h fp16 + exp-factor score tables.
// ---------------------------------------------------------------------------
__global__ __launch_bounds__(256) void k1_h(const float* __restrict__ x,
                                            const float* __restrict__ W,
                                            const float* __restrict__ a) {
    __shared__ float As[64][36];
    __shared__ float Bs[32][136];
    __shared__ float red[64][2];
    int tid = threadIdx.x;
    int lane = tid & 31, w = tid >> 5;
    int wm = w >> 2, wn = w & 3;
    int g = lane >> 2, tg = lane & 3;
    long i0 = (long)blockIdx.x * 64;

    float2 asv[4], adv[4];
#pragma unroll
    for (int nt = 0; nt < 4; nt++) {
        int c = wn * 32 + nt * 8 + 2 * tg;
        asv[nt].x = __ldg(a + c);       asv[nt].y = __ldg(a + c + 1);
        adv[nt].x = __ldg(a + 128 + c); adv[nt].y = __ldg(a + 128 + c + 1);
    }
    if (tid < 128) ((float*)red)[tid] = 0.f;

    float acc[2][4][4];
#pragma unroll
    for (int mt = 0; mt < 2; mt++)
#pragma unroll
        for (int nt = 0; nt < 4; nt++)
#pragma unroll
            for (int q = 0; q < 4; q++) acc[mt][nt][q] = 0.f;

#pragma unroll
    for (int kc = 0; kc < 4; kc++) {
        int k0 = kc * 32;
        __syncthreads();
#pragma unroll
        for (int t = 0; t < 2; t++) {
            int e = tid + t * 256;
            int r = e >> 3, c4 = (e & 7) * 4;
            float4 xv = *(const float4*)(x + (i0 + r) * 128 + k0 + c4);
            uint4 o;
            o.x = f2tf(xv.x); o.y = f2tf(xv.y); o.z = f2tf(xv.z); o.w = f2tf(xv.w);
            *(uint4*)&As[r][c4] = o;
        }
#pragma unroll
        for (int t = 0; t < 4; t++) {
            int f = tid + t * 256;
            int r = f >> 5, c4 = (f & 31) * 4;
            float4 wv = *(const float4*)(W + (k0 + r) * 128 + c4);
            uint4 o;
            o.x = f2tf(wv.x); o.y = f2tf(wv.y); o.z = f2tf(wv.z); o.w = f2tf(wv.w);
            *(uint4*)&Bs[r][c4] = o;
        }
        __syncthreads();
#pragma unroll
        for (int ks = 0; ks < 4; ks++) {
            int ka = ks * 8;
            uint32_t af[2][4], bf[4][2];
#pragma unroll
            for (int mt = 0; mt < 2; mt++) {
                int rA = wm * 32 + mt * 16 + g;
                af[mt][0] = __float_as_uint(As[rA][ka + tg]);
                af[mt][1] = __float_as_uint(As[rA + 8][ka + tg]);
                af[mt][2] = __float_as_uint(As[rA][ka + tg + 4]);
                af[mt][3] = __float_as_uint(As[rA + 8][ka + tg + 4]);
            }
#pragma unroll
            for (int nt = 0; nt < 4; nt++) {
                int cB = wn * 32 + nt * 8 + g;
                bf[nt][0] = __float_as_uint(Bs[ka + tg][cB]);
                bf[nt][1] = __float_as_uint(Bs[ka + tg + 4][cB]);
            }
#pragma unroll
            for (int mt = 0; mt < 2; mt++)
#pragma unroll
                for (int nt = 0; nt < 4; nt++) mma8(acc[mt][nt], af[mt], bf[nt]);
        }
    }

    // store h fp16
#pragma unroll
    for (int mt = 0; mt < 2; mt++)
#pragma unroll
        for (int nt = 0; nt < 4; nt++) {
            long r = i0 + wm * 32 + mt * 16 + g;
            int c = wn * 32 + nt * 8 + 2 * tg;
            *(__half2*)(g_hh + r * 128 + c) = __floats2half2_rn(acc[mt][nt][0], acc[mt][nt][1]);
            *(__half2*)(g_hh + (r + 8) * 128 + c) = __floats2half2_rn(acc[mt][nt][2], acc[mt][nt][3]);
        }

    // scores via shfl + smem-atomic reduction, then exp tables
    __syncthreads();
#pragma unroll
    for (int mt = 0; mt < 2; mt++)
#pragma unroll
        for (int half = 0; half < 2; half++) {
            int rl = wm * 32 + mt * 16 + g + 8 * half;
            float s = 0.f, d = 0.f;
#pragma unroll
            for (int nt = 0; nt < 4; nt++) {
                float v0 = acc[mt][nt][2 * half];
                float v1 = acc[mt][nt][2 * half + 1];
                s += v0 * asv[nt].x + v1 * asv[nt].y;
                d += v0 * adv[nt].x + v1 * adv[nt].y;
            }
            s += __shfl_xor_sync(0xFFFFFFFFu, s, 1);
            s += __shfl_xor_sync(0xFFFFFFFFu, s, 2);
            d += __shfl_xor_sync(0xFFFFFFFFu, d, 1);
            d += __shfl_xor_sync(0xFFFFFFFFu, d, 2);
            if (tg == 0) {
                atomicAdd(&red[rl][0], s);
                atomicAdd(&red[rl][1], d);
            }
        }
    __syncthreads();
    if (tid < 64) {
        float s = red[tid][0], d = red[tid][1];
        g_e1s[i0 + tid] = __expf(s);
        g_e2s[i0 + tid] = __expf(NEG_SLOPE * s);
        g_thr[i0 + tid] = __expf(-s);
        g_e1d[i0 + tid] = __expf(d);
        g_e2d[i0 + tid] = __expf(NEG_SLOPE * d);
    }
}

// ---------------------------------------------------------------------------
// K2: invd[i] = 1 / (e1s_i * sum_{e1d_j>thr_i} e1d_j + e2s_i * sum_else e2d_j)
// ---------------------------------------------------------------------------
__global__ __launch_bounds__(256) void k2_den() {
    __shared__ float sd1[2048];
    __shared__ float sd2[2048];
    __shared__ float2 part[256];
    int tid = threadIdx.x;
    int b = blockIdx.x >> 5, ic = blockIdx.x & 31;
#pragma unroll
    for (int t = 0; t < 2; t++) {
        int f = tid + t * 256;
        *(float4*)&sd1[f * 4] = *(const float4*)(g_e1d + b * 2048 + f * 4);
        *(float4*)&sd2[f * 4] = *(const float4*)(g_e2d + b * 2048 + f * 4);
    }
    int r = tid & 63, q = tid >> 6;
    int row = b * 2048 + ic * 64 + r;
    float thr = g_thr[row];
    __syncthreads();
    float a1 = 0.f, a2 = 0.f;
    int j0 = q * 512;
#pragma unroll 8
    for (int j = 0; j < 512; j++) {
        float v1 = sd1[j0 + j];
        float v2 = sd2[j0 + j];
        bool c = v1 > thr;
        a1 += c ? v1 : 0.f;
        a2 += c ? 0.f : v2;
    }
    part[tid] = make_float2(a1, a2);
    __syncthreads();
    if (tid < 64) {
        float2 p0 = part[tid], p1 = part[tid + 64], p2 = part[tid + 128], p3 = part[tid + 192];
        float den = g_e1s[row] * (p0.x + p1.x + p2.x + p3.x) +
                    g_e2s[row] * (p0.y + p1.y + p2.y + p3.y);
        g_invd[row] = 1.f / den;
    }
}

// ---------------------------------------------------------------------------
// K3: out = lrelu( (adj + softmax-term) @ h ), warp-specialized fp16 GEMM.
// 512 threads: warps 0-7 consume (m16n8k16 + ldmatrix), warps 8-15 produce
// (1 row x 16 cols per thread). adj via 4-deep cp.async ring, one commit
// group per chunk {adj(c+3), B(c+3)}, wait_group 3.
// Named barriers: full[s]=1+s, free[s]=5+s, count 512.
// ---------------------------------------------------------------------------
struct SmemK3 {
    float  adjS[4][128][32];   // adj staging (fp32), 128B rows
    __half A[4][128][40];      // coeff tiles fp16, 80B rows (pad)
    __half Bt[4][32][136];     // h tiles fp16, 272B rows (pad)
    float  e1[2048];
    float  e2[2048];
};

__global__ __launch_bounds__(512) void k3_main(const float* __restrict__ adj,
                                               float* __restrict__ out) {
    extern __shared__ char smraw[];
    SmemK3& sm = *(SmemK3*)smraw;
    int tid = threadIdx.x, lane = tid & 31, w = tid >> 5;
    int b = blockIdx.y;
    int i0 = blockIdx.x * 128;
    const float* adjb = adj + ((long)b * 2048 + i0) * 2048;
    const __half* hhb = g_hh + (long)b * 2048 * 128;

    // all threads: load e1d/e2d tables, then one full sync
    for (int f = tid; f < 512; f += 512) {
        *(float4*)&sm.e1[f * 4] = *(const float4*)(g_e1d + b * 2048 + f * 4);
        *(float4*)&sm.e2[f * 4] = *(const float4*)(g_e2d + b * 2048 + f * 4);
    }
    __syncthreads();

    if (w >= 8) {
        // ================= PRODUCERS (warps 8-15, 256 threads) =============
        int ptid = tid - 256;
        int pr = ptid >> 1;          // row 0..127
        int ph = ptid & 1;           // col half: floats ph*16 .. ph*16+15
        int gr = b * 2048 + i0 + pr;
        float iv = g_invd[gr];
        float p1 = g_e1s[gr] * iv;
        float p2 = g_e2s[gr] * iv;
        float th = g_thr[gr];

        // prologue: groups for chunks 0,1,2 ({adj,B} each)
#pragma unroll
        for (int s = 0; s < 3; s++) {
#pragma unroll
            for (int q = 0; q < 4; q++)
                cp16(&sm.adjS[s][pr][ph * 16 + q * 4],
                     adjb + (long)pr * 2048 + s * 32 + ph * 16 + q * 4);
#pragma unroll
            for (int k = 0; k < 2; k++) {
                int f = ptid + k * 256;
                int r = f >> 4, cc = f & 15;
                cp16(&sm.Bt[s][r][cc * 8], hhb + (long)(s * 32 + r) * 128 + cc * 8);
            }
            cp_commit();
        }

        for (int c = 0; c < 64; c++) {
            int s = c & 3;
            // free stage for chunk c+3 (consumers done with chunk c-1)
            if (c >= 1 && c + 3 < 64) bar_sync(5 + ((c + 3) & 3), 512);
            // issue group for chunk c+3
            if (c + 3 < 64) {
                int sn = (c + 3) & 3;
#pragma unroll
                for (int q = 0; q < 4; q++)
                    cp16(&sm.adjS[sn][pr][ph * 16 + q * 4],
                         adjb + (long)pr * 2048 + (c + 3) * 32 + ph * 16 + q * 4);
#pragma unroll
                for (int k = 0; k < 2; k++) {
                    int f = ptid + k * 256;
                    int r = f >> 4, cc = f & 15;
                    cp16(&sm.Bt[sn][r][cc * 8],
                         hhb + (long)((c + 3) * 32 + r) * 128 + cc * 8);
                }
                cp_commit();
            }
            // wait until group c (adjS(c), Bt(c)) landed
            if (c <= 60)      asm volatile("cp.async.wait_group 3;" ::: "memory");
            else if (c == 61) asm volatile("cp.async.wait_group 2;" ::: "memory");
            else if (c == 62) asm volatile("cp.async.wait_group 1;" ::: "memory");
            else              asm volatile("cp.async.wait_group 0;" ::: "memory");

            // coeff for chunk c: 1 row x 16 cols -> A[s] (fp16)
#pragma unroll
            for (int q = 0; q < 4; q++) {
                int cf = ph * 16 + q * 4;
                float4 av = *(const float4*)&sm.adjS[s][pr][cf];
                float4 v1 = *(const float4*)&sm.e1[c * 32 + cf];
                float4 v2 = *(const float4*)&sm.e2[c * 32 + cf];
                float c0 = fmaf(v1.x > th ? p1 : p2, v1.x > th ? v1.x : v2.x, av.x);
                float c1 = fmaf(v1.y > th ? p1 : p2, v1.y > th ? v1.y : v2.y, av.y);
                float c2 = fmaf(v1.z > th ? p1 : p2, v1.z > th ? v1.z : v2.z, av.z);
                float c3 = fmaf(v1.w > th ? p1 : p2, v1.w > th ? v1.w : v2.w, av.w);
                __half2 h0 = __floats2half2_rn(c0, c1);
                __half2 h1 = __floats2half2_rn(c2, c3);
                uint2 u;
                u.x = *(uint32_t*)&h0;
                u.y = *(uint32_t*)&h1;
                *(uint2*)&sm.A[s][pr][cf] = u;
            }
            bar_arrive(1 + s, 512);
        }
    } else {
        // ================= CONSUMERS (warps 0-7, 256 threads) ==============
        int wr = w & 3, wc = w >> 2;
        int grp = lane >> 2, tg = lane & 3;
        uint32_t aBase = (uint32_t)__cvta_generic_to_shared(&sm.A[0][0][0]);
        uint32_t bBase = (uint32_t)__cvta_generic_to_shared(&sm.Bt[0][0][0]);
        const uint32_t A_ST = 128 * 40 * 2, B_ST = 32 * 136 * 2;

        float acc[2][8][4];
#pragma unroll
        for (int mt = 0; mt < 2; mt++)
#pragma unroll
            for (int ng = 0; ng < 8; ng++)
#pragma unroll
                for (int q = 0; q < 4; q++) acc[mt][ng][q] = 0.f;

        int aRow = wr * 32 + (lane & 15);
        int aColB = (lane >> 4) * 16;
        int bRowBase = ((lane >> 3) & 1) * 8 + (lane & 7);
        int bColH = wc * 64 + (lane >> 4) * 8;

        for (int c = 0; c < 64; c++) {
            int s = c & 3;
            bar_sync(1 + s, 512);
            uint32_t aS = aBase + s * A_ST;
            uint32_t bS = bBase + s * B_ST;
#pragma unroll
            for (int ks = 0; ks < 2; ks++) {
                uint32_t afr[2][4], bfr[4][4];
#pragma unroll
                for (int mt = 0; mt < 2; mt++) {
                    uint32_t addr = aS + (uint32_t)((aRow + mt * 16) * 80 + ks * 32) + aColB;
                    ldsm4(afr[mt], addr);
                }
#pragma unroll
                for (int ng2 = 0; ng2 < 4; ng2++) {
                    uint32_t addr = bS + (uint32_t)((bRowBase + ks * 16) * 272 +
                                                    (bColH + ng2 * 16) * 2);
                    ldsm4t(bfr[ng2], addr);
                }
#pragma unroll
                for (int mt = 0; mt < 2; mt++)
#pragma unroll
                    for (int ng2 = 0; ng2 < 4; ng2++) {
                        mma16(acc[mt][ng2 * 2], afr[mt], bfr[ng2][0], bfr[ng2][1]);
                        mma16(acc[mt][ng2 * 2 + 1], afr[mt], bfr[ng2][2], bfr[ng2][3]);
                    }
            }
            if (c + 1 < 64) bar_arrive(5 + s, 512);
        }

        // epilogue: lrelu + store (float2 per pair)
#pragma unroll
        for (int mt = 0; mt < 2; mt++)
#pragma unroll
            for (int rh = 0; rh < 2; rh++) {
                int rloc = wr * 32 + mt * 16 + grp + 8 * rh;
                long grow = (long)b * 2048 + i0 + rloc;
#pragma unroll
                for (int ng = 0; ng < 8; ng++) {
                    int col = wc * 64 + ng * 8 + 2 * tg;
                    float2 vv;
                    vv.x = lrelu(acc[mt][ng][2 * rh]);
                    vv.y = lrelu(acc[mt][ng][2 * rh + 1]);
                    *(float2*)(out + grow * 128 + col) = vv;
                }
            }
    }
}

// ---------------------------------------------------------------------------
extern "C" void kernel_launch(void* const* d_in, const int* in_sizes, int n_in,
                              void* d_out, int out_size) {
    (void)in_sizes; (void)n_in; (void)out_size;
    const float* x   = (const float*)d_in[0];
    const float* adj = (const float*)d_in[1];
    const float* W   = (const float*)d_in[2];
    const float* a   = (const float*)d_in[3];
    float* out = (float*)d_out;

    k1_h<<<256, 256>>>(x, W, a);
    k2_den<<<256, 256>>>();
    cudaFuncSetAttribute(k3_main, cudaFuncAttributeMaxDynamicSharedMemorySize,
                         (int)sizeof(SmemK3));
    k3_main<<<dim3(16, 8), 512, sizeof(SmemK3)>>>(adj, out);
}

// round 12
// speedup vs baseline: 1.0201x; 1.0201x over previous
#include <cuda_runtime.h>
#include <cuda_fp16.h>
#include <cstdint>

#define NEG_SLOPE 0.2f

static constexpr int Bb = 8;
static constexpr int Nn = 2048;
static constexpr int Dd = 128;

// Scratch (device globals; allocation-free rule)
__device__ __half g_hh[Bb * Nn * Dd];    // h fp16 (GEMM B operand)
__device__ float  g_e1s[Bb * Nn];        // exp(s_src)
__device__ float  g_e2s[Bb * Nn];        // exp(0.2*s_src)
__device__ float  g_e1d[Bb * Nn];        // exp(s_dst)
__device__ float  g_e2d[Bb * Nn];        // exp(0.2*s_dst)
__device__ float  g_thr[Bb * Nn];        // exp(-s_src)  (cond: e1d_j > thr_i)
__device__ float  g_invd[Bb * Nn];

__device__ __forceinline__ uint32_t f2tf(float x) {
    uint32_t r;
    asm("cvt.rna.tf32.f32 %0, %1;" : "=r"(r) : "f"(x));
    return r;
}
__device__ __forceinline__ float lrelu(float v) { return v > 0.f ? v : NEG_SLOPE * v; }

__device__ __forceinline__ void mma8(float* d, const uint32_t* a, const uint32_t* b) {
    asm volatile(
        "mma.sync.aligned.m16n8k8.row.col.f32.tf32.tf32.f32 "
        "{%0,%1,%2,%3},{%4,%5,%6,%7},{%8,%9},{%0,%1,%2,%3};\n"
        : "+f"(d[0]), "+f"(d[1]), "+f"(d[2]), "+f"(d[3])
        : "r"(a[0]), "r"(a[1]), "r"(a[2]), "r"(a[3]), "r"(b[0]), "r"(b[1]));
}
__device__ __forceinline__ void mma16(float* d, const uint32_t* a, uint32_t b0, uint32_t b1) {
    asm volatile(
        "mma.sync.aligned.m16n8k16.row.col.f32.f16.f16.f32 "
        "{%0,%1,%2,%3},{%4,%5,%6,%7},{%8,%9},{%0,%1,%2,%3};\n"
        : "+f"(d[0]), "+f"(d[1]), "+f"(d[2]), "+f"(d[3])
        : "r"(a[0]), "r"(a[1]), "r"(a[2]), "r"(a[3]), "r"(b0), "r"(b1));
}
__device__ __forceinline__ void ldsm4(uint32_t* r, uint32_t a) {
    asm volatile("ldmatrix.sync.aligned.m8n8.x4.shared.b16 {%0,%1,%2,%3}, [%4];"
                 : "=r"(r[0]), "=r"(r[1]), "=r"(r[2]), "=r"(r[3]) : "r"(a));
}
__device__ __forceinline__ void ldsm4t(uint32_t* r, uint32_t a) {
    asm volatile("ldmatrix.sync.aligned.m8n8.x4.trans.shared.b16 {%0,%1,%2,%3}, [%4];"
                 : "=r"(r[0]), "=r"(r[1]), "=r"(r[2]), "=r"(r[3]) : "r"(a));
}
__device__ __forceinline__ void cp16(void* s, const void* g) {
    uint32_t sa = (uint32_t)__cvta_generic_to_shared(s);
    asm volatile("cp.async.cg.shared.global [%0], [%1], 16;" :: "r"(sa), "l"(g));
}
__device__ __forceinline__ void cp_commit() { asm volatile("cp.async.commit_group;"); }
__device__ __forceinline__ void bar_sync(int id, int cnt) {
    asm volatile("bar.sync %0, %1;" :: "r"(id), "r"(cnt) : "memory");
}
__device__ __forceinline__ void bar_arrive(int id, int cnt) {
    asm volatile("bar.arrive %0, %1;" :: "r"(id), "r"(cnt) : "memory");
}

// ---------------------------------------------------------------------------
// K1: h = x @ W (tf32 mma.sync). Stores h fp16 + exp-factor score tables.
// ---------------------------------------------------------------------------
__global__ __launch_bounds__(256) void k1_h(const float* __restrict__ x,
                                            const float* __restrict__ W,
                                            const float* __restrict__ a) {
    __shared__ float As[64][36];
    __shared__ float Bs[32][136];
    __shared__ float red[64][2];
    int tid = threadIdx.x;
    int lane = tid & 31, w = tid >> 5;
    int wm = w >> 2, wn = w & 3;
    int g = lane >> 2, tg = lane & 3;
    long i0 = (long)blockIdx.x * 64;

    float2 asv[4], adv[4];
#pragma unroll
    for (int nt = 0; nt < 4; nt++) {
        int c = wn * 32 + nt * 8 + 2 * tg;
        asv[nt].x = __ldg(a + c);       asv[nt].y = __ldg(a + c + 1);
        adv[nt].x = __ldg(a + 128 + c); adv[nt].y = __ldg(a + 128 + c + 1);
    }
    if (tid < 128) ((float*)red)[tid] = 0.f;

    float acc[2][4][4];
#pragma unroll
    for (int mt = 0; mt < 2; mt++)
#pragma unroll
        for (int nt = 0; nt < 4; nt++)
#pragma unroll
            for (int q = 0; q < 4; q++) acc[mt][nt][q] = 0.f;

#pragma unroll
    for (int kc = 0; kc < 4; kc++) {
        int k0 = kc * 32;
        __syncthreads();
#pragma unroll
        for (int t = 0; t < 2; t++) {
            int e = tid + t * 256;
            int r = e >> 3, c4 = (e & 7) * 4;
            float4 xv = *(const float4*)(x + (i0 + r) * 128 + k0 + c4);
            uint4 o;
            o.x = f2tf(xv.x); o.y = f2tf(xv.y); o.z = f2tf(xv.z); o.w = f2tf(xv.w);
            *(uint4*)&As[r][c4] = o;
        }
#pragma unroll
        for (int t = 0; t < 4; t++) {
            int f = tid + t * 256;
            int r = f >> 5, c4 = (f & 31) * 4;
            float4 wv = *(const float4*)(W + (k0 + r) * 128 + c4);
            uint4 o;
            o.x = f2tf(wv.x); o.y = f2tf(wv.y); o.z = f2tf(wv.z); o.w = f2tf(wv.w);
            *(uint4*)&Bs[r][c4] = o;
        }
        __syncthreads();
#pragma unroll
        for (int ks = 0; ks < 4; ks++) {
            int ka = ks * 8;
            uint32_t af[2][4], bf[4][2];
#pragma unroll
            for (int mt = 0; mt < 2; mt++) {
                int rA = wm * 32 + mt * 16 + g;
                af[mt][0] = __float_as_uint(As[rA][ka + tg]);
                af[mt][1] = __float_as_uint(As[rA + 8][ka + tg]);
                af[mt][2] = __float_as_uint(As[rA][ka + tg + 4]);
                af[mt][3] = __float_as_uint(As[rA + 8][ka + tg + 4]);
            }
#pragma unroll
            for (int nt = 0; nt < 4; nt++) {
                int cB = wn * 32 + nt * 8 + g;
                bf[nt][0] = __float_as_uint(Bs[ka + tg][cB]);
                bf[nt][1] = __float_as_uint(Bs[ka + tg + 4][cB]);
            }
#pragma unroll
            for (int mt = 0; mt < 2; mt++)
#pragma unroll
                for (int nt = 0; nt < 4; nt++) mma8(acc[mt][nt], af[mt], bf[nt]);
        }
    }

    // store h fp16
#pragma unroll
    for (int mt = 0; mt < 2; mt++)
#pragma unroll
        for (int nt = 0; nt < 4; nt++) {
            long r = i0 + wm * 32 + mt * 16 + g;
            int c = wn * 32 + nt * 8 + 2 * tg;
            *(__half2*)(g_hh + r * 128 + c) = __floats2half2_rn(acc[mt][nt][0], acc[mt][nt][1]);
            *(__half2*)(g_hh + (r + 8) * 128 + c) = __floats2half2_rn(acc[mt][nt][2], acc[mt][nt][3]);
        }

    // scores via shfl + smem-atomic reduction, then exp tables
    __syncthreads();
#pragma unroll
    for (int mt = 0; mt < 2; mt++)
#pragma unroll
        for (int half = 0; half < 2; half++) {
            int rl = wm * 32 + mt * 16 + g + 8 * half;
            float s = 0.f, d = 0.f;
#pragma unroll
            for (int nt = 0; nt < 4; nt++) {
                float v0 = acc[mt][nt][2 * half];
                float v1 = acc[mt][nt][2 * half + 1];
                s += v0 * asv[nt].x + v1 * asv[nt].y;
                d += v0 * adv[nt].x + v1 * adv[nt].y;
            }
            s += __shfl_xor_sync(0xFFFFFFFFu, s, 1);
            s += __shfl_xor_sync(0xFFFFFFFFu, s, 2);
            d += __shfl_xor_sync(0xFFFFFFFFu, d, 1);
            d += __shfl_xor_sync(0xFFFFFFFFu, d, 2);
            if (tg == 0) {
                atomicAdd(&red[rl][0], s);
                atomicAdd(&red[rl][1], d);
            }
        }
    __syncthreads();
    if (tid < 64) {
        float s = red[tid][0], d = red[tid][1];
        g_e1s[i0 + tid] = __expf(s);
        g_e2s[i0 + tid] = __expf(NEG_SLOPE * s);
        g_thr[i0 + tid] = __expf(-s);
        g_e1d[i0 + tid] = __expf(d);
        g_e2d[i0 + tid] = __expf(NEG_SLOPE * d);
    }
}

// ---------------------------------------------------------------------------
// K2: invd[i] = 1 / (e1s_i * sum_{e1d_j>thr_i} e1d_j + e2s_i * sum_else e2d_j)
// ---------------------------------------------------------------------------
__global__ __launch_bounds__(256) void k2_den() {
    __shared__ float sd1[2048];
    __shared__ float sd2[2048];
    __shared__ float2 part[256];
    int tid = threadIdx.x;
    int b = blockIdx.x >> 5, ic = blockIdx.x & 31;
#pragma unroll
    for (int t = 0; t < 2; t++) {
        int f = tid + t * 256;
        *(float4*)&sd1[f * 4] = *(const float4*)(g_e1d + b * 2048 + f * 4);
        *(float4*)&sd2[f * 4] = *(const float4*)(g_e2d + b * 2048 + f * 4);
    }
    int r = tid & 63, q = tid >> 6;
    int row = b * 2048 + ic * 64 + r;
    float thr = g_thr[row];
    __syncthreads();
    float a1 = 0.f, a2 = 0.f;
    int j0 = q * 512;
#pragma unroll 8
    for (int j = 0; j < 512; j++) {
        float v1 = sd1[j0 + j];
        float v2 = sd2[j0 + j];
        bool c = v1 > thr;
        a1 += c ? v1 : 0.f;
        a2 += c ? 0.f : v2;
    }
    part[tid] = make_float2(a1, a2);
    __syncthreads();
    if (tid < 64) {
        float2 p0 = part[tid], p1 = part[tid + 64], p2 = part[tid + 128], p3 = part[tid + 192];
        float den = g_e1s[row] * (p0.x + p1.x + p2.x + p3.x) +
                    g_e2s[row] * (p0.y + p1.y + p2.y + p3.y);
        g_invd[row] = 1.f / den;
    }
}

// ---------------------------------------------------------------------------
// K3: out = lrelu( (adj + softmax-term) @ h ), warp-specialized fp16 GEMM.
// M-tile = 64 rows per CTA -> smem ~102 KB -> 2 CTAs/SM (overhead overlap).
// 384 threads: warps 0-7 consume (32x32 warp tiles), warps 8-11 produce
// (1 row x 16 cols per thread). adj via 4-deep cp.async ring, one commit
// group per chunk {adj(c+3), B(c+3)}, wait_group 3.
// Named barriers: full[s]=1+s, free[s]=5+s, count 384.
// ---------------------------------------------------------------------------
struct SmemK3 {
    float  adjS[4][64][32];    // adj staging (fp32), 128B rows
    __half A[4][64][40];       // coeff tiles fp16, 80B rows (pad)
    __half Bt[4][32][136];     // h tiles fp16, 272B rows (pad)
    float  e1[2048];
    float  e2[2048];
};

__global__ __launch_bounds__(384, 2) void k3_main(const float* __restrict__ adj,
                                                  float* __restrict__ out) {
    extern __shared__ char smraw[];
    SmemK3& sm = *(SmemK3*)smraw;
    int tid = threadIdx.x, lane = tid & 31, w = tid >> 5;
    int b = blockIdx.y;
    int i0 = blockIdx.x * 64;
    const float* adjb = adj + ((long)b * 2048 + i0) * 2048;
    const __half* hhb = g_hh + (long)b * 2048 * 128;

    // all threads: load e1d/e2d tables, then one full sync
    for (int f = tid; f < 512; f += 384) {
        *(float4*)&sm.e1[f * 4] = *(const float4*)(g_e1d + b * 2048 + f * 4);
        *(float4*)&sm.e2[f * 4] = *(const float4*)(g_e2d + b * 2048 + f * 4);
    }
    __syncthreads();

    if (w >= 8) {
        // ================= PRODUCERS (warps 8-11, 128 threads) =============
        int ptid = tid - 256;
        int pr = ptid >> 1;          // row 0..63
        int ph = ptid & 1;           // col half: floats ph*16 .. ph*16+15
        int gr = b * 2048 + i0 + pr;
        float iv = g_invd[gr];
        float p1 = g_e1s[gr] * iv;
        float p2 = g_e2s[gr] * iv;
        float th = g_thr[gr];

        // prologue: groups for chunks 0,1,2 ({adj,B} each)
#pragma unroll
        for (int s = 0; s < 3; s++) {
#pragma unroll
            for (int q = 0; q < 4; q++)
                cp16(&sm.adjS[s][pr][ph * 16 + q * 4],
                     adjb + (long)pr * 2048 + s * 32 + ph * 16 + q * 4);
#pragma unroll
            for (int k = 0; k < 4; k++) {
                int f = ptid + k * 128;
                int r = f >> 4, cc = f & 15;
                cp16(&sm.Bt[s][r][cc * 8], hhb + (long)(s * 32 + r) * 128 + cc * 8);
            }
            cp_commit();
        }

        for (int c = 0; c < 64; c++) {
            int s = c & 3;
            // free stage for chunk c+3 (consumers done with chunk c-1)
            if (c >= 1 && c + 3 < 64) bar_sync(5 + ((c + 3) & 3), 384);
            // issue group for chunk c+3
            if (c + 3 < 64) {
                int sn = (c + 3) & 3;
#pragma unroll
                for (int q = 0; q < 4; q++)
                    cp16(&sm.adjS[sn][pr][ph * 16 + q * 4],
                         adjb + (long)pr * 2048 + (c + 3) * 32 + ph * 16 + q * 4);
#pragma unroll
                for (int k = 0; k < 4; k++) {
                    int f = ptid + k * 128;
                    int r = f >> 4, cc = f & 15;
                    cp16(&sm.Bt[sn][r][cc * 8],
                         hhb + (long)((c + 3) * 32 + r) * 128 + cc * 8);
                }
                cp_commit();
            }
            // wait until group c (adjS(c), Bt(c)) landed
            if (c <= 60)      asm volatile("cp.async.wait_group 3;" ::: "memory");
            else if (c == 61) asm volatile("cp.async.wait_group 2;" ::: "memory");
            else if (c == 62) asm volatile("cp.async.wait_group 1;" ::: "memory");
            else              asm volatile("cp.async.wait_group 0;" ::: "memory");

            // coeff for chunk c: 1 row x 16 cols -> A[s] (fp16)
#pragma unroll
            for (int q = 0; q < 4; q++) {
                int cf = ph * 16 + q * 4;
                float4 av = *(const float4*)&sm.adjS[s][pr][cf];
                float4 v1 = *(const float4*)&sm.e1[c * 32 + cf];
                float4 v2 = *(const float4*)&sm.e2[c * 32 + cf];
                float c0 = fmaf(v1.x > th ? p1 : p2, v1.x > th ? v1.x : v2.x, av.x);
                float c1 = fmaf(v1.y > th ? p1 : p2, v1.y > th ? v1.y : v2.y, av.y);
                float c2 = fmaf(v1.z > th ? p1 : p2, v1.z > th ? v1.z : v2.z, av.z);
                float c3 = fmaf(v1.w > th ? p1 : p2, v1.w > th ? v1.w : v2.w, av.w);
                __half2 h0 = __floats2half2_rn(c0, c1);
                __half2 h1 = __floats2half2_rn(c2, c3);
                uint2 u;
                u.x = *(uint32_t*)&h0;
                u.y = *(uint32_t*)&h1;
                *(uint2*)&sm.A[s][pr][cf] = u;
            }
            bar_arrive(1 + s, 384);
        }
    } else {
        // ================= CONSUMERS (warps 0-7, 256 threads) ==============
        int wr = w & 1, wc = w >> 1;   // rows wr*32.., cols wc*32..
        int grp = lane >> 2, tg = lane & 3;
        uint32_t aBase = (uint32_t)__cvta_generic_to_shared(&sm.A[0][0][0]);
        uint32_t bBase = (uint32_t)__cvta_generic_to_shared(&sm.Bt[0][0][0]);
        const uint32_t A_ST = 64 * 40 * 2, B_ST = 32 * 136 * 2;

        float acc[2][4][4];
#pragma unroll
        for (int mt = 0; mt < 2; mt++)
#pragma unroll
            for (int ng = 0; ng < 4; ng++)
#pragma unroll
                for (int q = 0; q < 4; q++) acc[mt][ng][q] = 0.f;

        int aRow = wr * 32 + (lane & 15);
        int aColB = (lane >> 4) * 16;
        int bRowBase = ((lane >> 3) & 1) * 8 + (lane & 7);
        int bColH = wc * 32 + (lane >> 4) * 8;

        for (int c = 0; c < 64; c++) {
            int s = c & 3;
            bar_sync(1 + s, 384);
            uint32_t aS = aBase + s * A_ST;
            uint32_t bS = bBase + s * B_ST;
#pragma unroll
            for (int ks = 0; ks < 2; ks++) {
                uint32_t afr[2][4], bfr[2][4];
#pragma unroll
                for (int mt = 0; mt < 2; mt++) {
                    uint32_t addr = aS + (uint32_t)((aRow + mt * 16) * 80 + ks * 32) + aColB;
                    ldsm4(afr[mt], addr);
                }
#pragma unroll
                for (int ng2 = 0; ng2 < 2; ng2++) {
                    uint32_t addr = bS + (uint32_t)((bRowBase + ks * 16) * 272 +
                                                    (bColH + ng2 * 16) * 2);
                    ldsm4t(bfr[ng2], addr);
                }
#pragma unroll
                for (int mt = 0; mt < 2; mt++)
#pragma unroll
                    for (int ng2 = 0; ng2 < 2; ng2++) {
                        mma16(acc[mt][ng2 * 2], afr[mt], bfr[ng2][0], bfr[ng2][1]);
                        mma16(acc[mt][ng2 * 2 + 1], afr[mt], bfr[ng2][2], bfr[ng2][3]);
                    }
            }
            if (c + 1 < 64) bar_arrive(5 + s, 384);
        }

        // epilogue: lrelu + store (float2 per pair)
#pragma unroll
        for (int mt = 0; mt < 2; mt++)
#pragma unroll
            for (int rh = 0; rh < 2; rh++) {
                int rloc = wr * 32 + mt * 16 + grp + 8 * rh;
                long grow = (long)b * 2048 + i0 + rloc;
#pragma unroll
                for (int ng = 0; ng < 4; ng++) {
                    int col = wc * 32 + ng * 8 + 2 * tg;
                    float2 vv;
                    vv.x = lrelu(acc[mt][ng][2 * rh]);
                    vv.y = lrelu(acc[mt][ng][2 * rh + 1]);
                    *(float2*)(out + grow * 128 + col) = vv;
                }
            }
    }
}

// ---------------------------------------------------------------------------
extern "C" void kernel_launch(void* const* d_in, const int* in_sizes, int n_in,
                              void* d_out, int out_size) {
    (void)in_sizes; (void)n_in; (void)out_size;
    const float* x   = (const float*)d_in[0];
    const float* adj = (const float*)d_in[1];
    const float* W   = (const float*)d_in[2];
    const float* a   = (const float*)d_in[3];
    float* out = (float*)d_out;

    k1_h<<<256, 256>>>(x, W, a);
    k2_den<<<256, 256>>>();
    cudaFuncSetAttribute(k3_main, cudaFuncAttributeMaxDynamicSharedMemorySize,
                         (int)sizeof(SmemK3));
    k3_main<<<dim3(32, 8), 384, sizeof(SmemK3)>>>(adj, out);
}

// round 13
// speedup vs baseline: 1.3067x; 1.2809x over previous
#include <cuda_runtime.h>
#include <cuda_fp16.h>
#include <cstdint>

#define NEG_SLOPE 0.2f

static constexpr int Bb = 8;
static constexpr int Nn = 2048;
static constexpr int Dd = 128;

// Scratch (device globals; allocation-free rule)
__device__ __half g_hh[Bb * Nn * Dd];    // h fp16 (GEMM B operand)
__device__ float  g_e1s[Bb * Nn];        // exp(s_src)
__device__ float  g_e2s[Bb * Nn];        // exp(0.2*s_src)
__device__ float  g_e1d[Bb * Nn];        // exp(s_dst)
__device__ float  g_e2d[Bb * Nn];        // exp(0.2*s_dst)
__device__ float  g_thr[Bb * Nn];        // exp(-s_src)  (cond: e1d_j > thr_i)
__device__ float  g_invd[Bb * Nn];

__device__ __forceinline__ uint32_t f2tf(float x) {
    uint32_t r;
    asm("cvt.rna.tf32.f32 %0, %1;" : "=r"(r) : "f"(x));
    return r;
}
__device__ __forceinline__ float lrelu(float v) { return v > 0.f ? v : NEG_SLOPE * v; }

__device__ __forceinline__ void mma8(float* d, const uint32_t* a, const uint32_t* b) {
    asm volatile(
        "mma.sync.aligned.m16n8k8.row.col.f32.tf32.tf32.f32 "
        "{%0,%1,%2,%3},{%4,%5,%6,%7},{%8,%9},{%0,%1,%2,%3};\n"
        : "+f"(d[0]), "+f"(d[1]), "+f"(d[2]), "+f"(d[3])
        : "r"(a[0]), "r"(a[1]), "r"(a[2]), "r"(a[3]), "r"(b[0]), "r"(b[1]));
}
__device__ __forceinline__ void mma16(float* d, const uint32_t* a, uint32_t b0, uint32_t b1) {
    asm volatile(
        "mma.sync.aligned.m16n8k16.row.col.f32.f16.f16.f32 "
        "{%0,%1,%2,%3},{%4,%5,%6,%7},{%8,%9},{%0,%1,%2,%3};\n"
        : "+f"(d[0]), "+f"(d[1]), "+f"(d[2]), "+f"(d[3])
        : "r"(a[0]), "r"(a[1]), "r"(a[2]), "r"(a[3]), "r"(b0), "r"(b1));
}
__device__ __forceinline__ void ldsm4(uint32_t* r, uint32_t a) {
    asm volatile("ldmatrix.sync.aligned.m8n8.x4.shared.b16 {%0,%1,%2,%3}, [%4];"
                 : "=r"(r[0]), "=r"(r[1]), "=r"(r[2]), "=r"(r[3]) : "r"(a));
}
__device__ __forceinline__ void ldsm4t(uint32_t* r, uint32_t a) {
    asm volatile("ldmatrix.sync.aligned.m8n8.x4.trans.shared.b16 {%0,%1,%2,%3}, [%4];"
                 : "=r"(r[0]), "=r"(r[1]), "=r"(r[2]), "=r"(r[3]) : "r"(a));
}
__device__ __forceinline__ void cp16(void* s, const void* g) {
    uint32_t sa = (uint32_t)__cvta_generic_to_shared(s);
    asm volatile("cp.async.cg.shared.global [%0], [%1], 16;" :: "r"(sa), "l"(g));
}
__device__ __forceinline__ void cp_commit() { asm volatile("cp.async.commit_group;"); }
__device__ __forceinline__ void bar_sync(int id, int cnt) {
    asm volatile("bar.sync %0, %1;" :: "r"(id), "r"(cnt) : "memory");
}
__device__ __forceinline__ void bar_arrive(int id, int cnt) {
    asm volatile("bar.arrive %0, %1;" :: "r"(id), "r"(cnt) : "memory");
}

// ---------------------------------------------------------------------------
// K1: h = x @ W (tf32 mma.sync), single K pass (whole K=128 in smem, 1 sync).
// Stores h fp16 + exp-factor score tables.
// ---------------------------------------------------------------------------
struct SmemK1 {
    float As[64][132];    // x tile, tf32 bits
    float Bs[128][136];   // full W, tf32 bits
    float red[64][2];
};

__global__ __launch_bounds__(256) void k1_h(const float* __restrict__ x,
                                            const float* __restrict__ W,
                                            const float* __restrict__ a) {
    extern __shared__ char smraw1[];
    SmemK1& sm = *(SmemK1*)smraw1;
    int tid = threadIdx.x;
    int lane = tid & 31, w = tid >> 5;
    int wm = w >> 2, wn = w & 3;
    int g = lane >> 2, tg = lane & 3;
    long i0 = (long)blockIdx.x * 64;

    float2 asv[4], adv[4];
#pragma unroll
    for (int nt = 0; nt < 4; nt++) {
        int c = wn * 32 + nt * 8 + 2 * tg;
        asv[nt].x = __ldg(a + c);       asv[nt].y = __ldg(a + c + 1);
        adv[nt].x = __ldg(a + 128 + c); adv[nt].y = __ldg(a + 128 + c + 1);
    }
    if (tid < 128) ((float*)sm.red)[tid] = 0.f;

    // load x tile (64x128) and full W (128x128), tf32-rounded
#pragma unroll
    for (int t = 0; t < 8; t++) {
        int e = tid + t * 256;
        int r = e >> 5, c4 = (e & 31) * 4;
        float4 xv = *(const float4*)(x + (i0 + r) * 128 + c4);
        uint4 o;
        o.x = f2tf(xv.x); o.y = f2tf(xv.y); o.z = f2tf(xv.z); o.w = f2tf(xv.w);
        *(uint4*)&sm.As[r][c4] = o;
    }
#pragma unroll
    for (int t = 0; t < 16; t++) {
        int f = tid + t * 256;
        int r = f >> 5, c4 = (f & 31) * 4;
        float4 wv = *(const float4*)(W + r * 128 + c4);
        uint4 o;
        o.x = f2tf(wv.x); o.y = f2tf(wv.y); o.z = f2tf(wv.z); o.w = f2tf(wv.w);
        *(uint4*)&sm.Bs[r][c4] = o;
    }
    __syncthreads();

    float acc[2][4][4];
#pragma unroll
    for (int mt = 0; mt < 2; mt++)
#pragma unroll
        for (int nt = 0; nt < 4; nt++)
#pragma unroll
            for (int q = 0; q < 4; q++) acc[mt][nt][q] = 0.f;

#pragma unroll
    for (int ks = 0; ks < 16; ks++) {
        int ka = ks * 8;
        uint32_t af[2][4], bf[4][2];
#pragma unroll
        for (int mt = 0; mt < 2; mt++) {
            int rA = wm * 32 + mt * 16 + g;
            af[mt][0] = __float_as_uint(sm.As[rA][ka + tg]);
            af[mt][1] = __float_as_uint(sm.As[rA + 8][ka + tg]);
            af[mt][2] = __float_as_uint(sm.As[rA][ka + tg + 4]);
            af[mt][3] = __float_as_uint(sm.As[rA + 8][ka + tg + 4]);
        }
#pragma unroll
        for (int nt = 0; nt < 4; nt++) {
            int cB = wn * 32 + nt * 8 + g;
            bf[nt][0] = __float_as_uint(sm.Bs[ka + tg][cB]);
            bf[nt][1] = __float_as_uint(sm.Bs[ka + tg + 4][cB]);
        }
#pragma unroll
        for (int mt = 0; mt < 2; mt++)
#pragma unroll
            for (int nt = 0; nt < 4; nt++) mma8(acc[mt][nt], af[mt], bf[nt]);
    }

    // store h fp16
#pragma unroll
    for (int mt = 0; mt < 2; mt++)
#pragma unroll
        for (int nt = 0; nt < 4; nt++) {
            long r = i0 + wm * 32 + mt * 16 + g;
            int c = wn * 32 + nt * 8 + 2 * tg;
            *(__half2*)(g_hh + r * 128 + c) = __floats2half2_rn(acc[mt][nt][0], acc[mt][nt][1]);
            *(__half2*)(g_hh + (r + 8) * 128 + c) = __floats2half2_rn(acc[mt][nt][2], acc[mt][nt][3]);
        }

    // scores via shfl + smem-atomic reduction, then exp tables
#pragma unroll
    for (int mt = 0; mt < 2; mt++)
#pragma unroll
        for (int half = 0; half < 2; half++) {
            int rl = wm * 32 + mt * 16 + g + 8 * half;
            float s = 0.f, d = 0.f;
#pragma unroll
            for (int nt = 0; nt < 4; nt++) {
                float v0 = acc[mt][nt][2 * half];
                float v1 = acc[mt][nt][2 * half + 1];
                s += v0 * asv[nt].x + v1 * asv[nt].y;
                d += v0 * adv[nt].x + v1 * adv[nt].y;
            }
            s += __shfl_xor_sync(0xFFFFFFFFu, s, 1);
            s += __shfl_xor_sync(0xFFFFFFFFu, s, 2);
            d += __shfl_xor_sync(0xFFFFFFFFu, d, 1);
            d += __shfl_xor_sync(0xFFFFFFFFu, d, 2);
            if (tg == 0) {
                atomicAdd(&sm.red[rl][0], s);
                atomicAdd(&sm.red[rl][1], d);
            }
        }
    __syncthreads();
    if (tid < 64) {
        float s = sm.red[tid][0], d = sm.red[tid][1];
        g_e1s[i0 + tid] = __expf(s);
        g_e2s[i0 + tid] = __expf(NEG_SLOPE * s);
        g_thr[i0 + tid] = __expf(-s);
        g_e1d[i0 + tid] = __expf(d);
        g_e2d[i0 + tid] = __expf(NEG_SLOPE * d);
    }
}

// ---------------------------------------------------------------------------
// K2: invd[i] = 1 / (e1s_i * sum_{e1d_j>thr_i} e1d_j + e2s_i * sum_else e2d_j)
// 512 blocks x 32 rows; 8 j-segments of 256 per row.
// ---------------------------------------------------------------------------
__global__ __launch_bounds__(256) void k2_den() {
    __shared__ float sd1[2048];
    __shared__ float sd2[2048];
    __shared__ float2 part[256];
    int tid = threadIdx.x;
    int b = blockIdx.x >> 6, ic = blockIdx.x & 63;
#pragma unroll
    for (int t = 0; t < 2; t++) {
        int f = tid + t * 256;
        *(float4*)&sd1[f * 4] = *(const float4*)(g_e1d + b * 2048 + f * 4);
        *(float4*)&sd2[f * 4] = *(const float4*)(g_e2d + b * 2048 + f * 4);
    }
    int r = tid & 31, q = tid >> 5;
    int row = b * 2048 + ic * 32 + r;
    float thr = g_thr[row];
    __syncthreads();
    float a1 = 0.f, a2 = 0.f;
    int j0 = q * 256;
#pragma unroll 8
    for (int j = 0; j < 256; j++) {
        float v1 = sd1[j0 + j];
        float v2 = sd2[j0 + j];
        bool c = v1 > thr;
        a1 += c ? v1 : 0.f;
        a2 += c ? 0.f : v2;
    }
    part[tid] = make_float2(a1, a2);
    __syncthreads();
    if (tid < 32) {
        float A1 = 0.f, A2 = 0.f;
#pragma unroll
        for (int k = 0; k < 8; k++) {
            float2 p = part[tid + 32 * k];
            A1 += p.x;
            A2 += p.y;
        }
        float den = g_e1s[row] * A1 + g_e2s[row] * A2;
        g_invd[row] = 1.f / den;
    }
}

// ---------------------------------------------------------------------------
// K3: out = lrelu( (adj + softmax-term) @ h ), warp-specialized fp16 GEMM.
// (byte-identical to the 78.6us R8 version)
// 384 threads: warps 0-7 consume (m16n8k16 + ldmatrix), warps 8-11 produce.
// adj via 4-deep cp.async ring; one commit group per chunk {adj(c+3), B(c+3)};
// wait_group 3. Named barriers: full[s]=1+s, free[s]=5+s, count 384.
// ---------------------------------------------------------------------------
struct SmemK3 {
    float  adjS[4][128][32];   // adj staging (fp32), 128B rows
    __half A[4][128][40];      // coeff tiles fp16, 80B rows (pad)
    __half Bt[4][32][136];     // h tiles fp16, 272B rows (pad)
    float  e1[2048];
    float  e2[2048];
};

__global__ __launch_bounds__(384) void k3_main(const float* __restrict__ adj,
                                               float* __restrict__ out) {
    extern __shared__ char smraw[];
    SmemK3& sm = *(SmemK3*)smraw;
    int tid = threadIdx.x, lane = tid & 31, w = tid >> 5;
    int b = blockIdx.y;
    int i0 = blockIdx.x * 128;
    const float* adjb = adj + ((long)b * 2048 + i0) * 2048;
    const __half* hhb = g_hh + (long)b * 2048 * 128;

    // all threads: load e1d/e2d tables, then one full sync
    for (int f = tid; f < 512; f += 384) {
        *(float4*)&sm.e1[f * 4] = *(const float4*)(g_e1d + b * 2048 + f * 4);
        *(float4*)&sm.e2[f * 4] = *(const float4*)(g_e2d + b * 2048 + f * 4);
    }
    __syncthreads();

    if (w >= 8) {
        // ================= PRODUCERS (warps 8-11, 128 threads) =============
        int ptid = tid - 256;
        int pr = ptid >> 3, pc8 = ptid & 7;   // rows pr+16t, 16B col chunk pc8
        float p1r[8], p2r[8], thrr[8];
#pragma unroll
        for (int t = 0; t < 8; t++) {
            int gr = b * 2048 + i0 + pr + 16 * t;
            float iv = g_invd[gr];
            p1r[t] = g_e1s[gr] * iv;
            p2r[t] = g_e2s[gr] * iv;
            thrr[t] = g_thr[gr];
        }
        // prologue: groups for chunks 0,1,2 ({adj,B} each)
#pragma unroll
        for (int s = 0; s < 3; s++) {
#pragma unroll
            for (int t = 0; t < 8; t++)
                cp16(&sm.adjS[s][pr + 16 * t][pc8 * 4],
                     adjb + (long)(pr + 16 * t) * 2048 + s * 32 + pc8 * 4);
#pragma unroll
            for (int k = 0; k < 4; k++) {
                int f = ptid + k * 128;
                int r = f >> 4, cc = f & 15;
                cp16(&sm.Bt[s][r][cc * 8], hhb + (long)(s * 32 + r) * 128 + cc * 8);
            }
            cp_commit();
        }

        for (int c = 0; c < 64; c++) {
            int s = c & 3;
            // free stage for chunk c+3 (consumers done with chunk c-1)
            if (c >= 1 && c + 3 < 64) bar_sync(5 + ((c + 3) & 3), 384);
            // issue group for chunk c+3
            if (c + 3 < 64) {
                int sn = (c + 3) & 3;
#pragma unroll
                for (int t = 0; t < 8; t++)
                    cp16(&sm.adjS[sn][pr + 16 * t][pc8 * 4],
                         adjb + (long)(pr + 16 * t) * 2048 + (c + 3) * 32 + pc8 * 4);
#pragma unroll
                for (int k = 0; k < 4; k++) {
                    int f = ptid + k * 128;
                    int r = f >> 4, cc = f & 15;
                    cp16(&sm.Bt[sn][r][cc * 8],
                         hhb + (long)((c + 3) * 32 + r) * 128 + cc * 8);
                }
                cp_commit();
            }
            // wait until group c (adjS(c), Bt(c)) landed
            if (c <= 60)      asm volatile("cp.async.wait_group 3;" ::: "memory");
            else if (c == 61) asm volatile("cp.async.wait_group 2;" ::: "memory");
            else if (c == 62) asm volatile("cp.async.wait_group 1;" ::: "memory");
            else              asm volatile("cp.async.wait_group 0;" ::: "memory");

            // coeff tile chunk c -> A[s] (fp16)
            float4 v1 = *(const float4*)&sm.e1[c * 32 + pc8 * 4];
            float4 v2 = *(const float4*)&sm.e2[c * 32 + pc8 * 4];
#pragma unroll
            for (int t = 0; t < 8; t++) {
                float4 av = *(const float4*)&sm.adjS[s][pr + 16 * t][pc8 * 4];
                float p1 = p1r[t], p2 = p2r[t], th = thrr[t];
                float c0 = fmaf(v1.x > th ? p1 : p2, v1.x > th ? v1.x : v2.x, av.x);
                float c1 = fmaf(v1.y > th ? p1 : p2, v1.y > th ? v1.y : v2.y, av.y);
                float c2 = fmaf(v1.z > th ? p1 : p2, v1.z > th ? v1.z : v2.z, av.z);
                float c3 = fmaf(v1.w > th ? p1 : p2, v1.w > th ? v1.w : v2.w, av.w);
                __half2 h0 = __floats2half2_rn(c0, c1);
                __half2 h1 = __floats2half2_rn(c2, c3);
                uint2 u;
                u.x = *(uint32_t*)&h0;
                u.y = *(uint32_t*)&h1;
                *(uint2*)&sm.A[s][pr + 16 * t][pc8 * 4] = u;
            }
            bar_arrive(1 + s, 384);
        }
    } else {
        // ================= CONSUMERS (warps 0-7, 256 threads) ==============
        int wr = w & 3, wc = w >> 2;
        int grp = lane >> 2, tg = lane & 3;
        uint32_t aBase = (uint32_t)__cvta_generic_to_shared(&sm.A[0][0][0]);
        uint32_t bBase = (uint32_t)__cvta_generic_to_shared(&sm.Bt[0][0][0]);
        const uint32_t A_ST = 128 * 40 * 2, B_ST = 32 * 136 * 2;

        float acc[2][8][4];
#pragma unroll
        for (int mt = 0; mt < 2; mt++)
#pragma unroll
            for (int ng = 0; ng < 8; ng++)
#pragma unroll
                for (int q = 0; q < 4; q++) acc[mt][ng][q] = 0.f;

        int aRow = wr * 32 + (lane & 15);
        int aColB = (lane >> 4) * 16;
        int bRowBase = ((lane >> 3) & 1) * 8 + (lane & 7);
        int bColH = wc * 64 + (lane >> 4) * 8;

        for (int c = 0; c < 64; c++) {
            int s = c & 3;
            bar_sync(1 + s, 384);
            uint32_t aS = aBase + s * A_ST;
            uint32_t bS = bBase + s * B_ST;
#pragma unroll
            for (int ks = 0; ks < 2; ks++) {
                uint32_t afr[2][4], bfr[4][4];
#pragma unroll
                for (int mt = 0; mt < 2; mt++) {
                    uint32_t addr = aS + (uint32_t)((aRow + mt * 16) * 80 + ks * 32) + aColB;
                    ldsm4(afr[mt], addr);
                }
#pragma unroll
                for (int ng2 = 0; ng2 < 4; ng2++) {
                    uint32_t addr = bS + (uint32_t)((bRowBase + ks * 16) * 272 +
                                                    (bColH + ng2 * 16) * 2);
                    ldsm4t(bfr[ng2], addr);
                }
#pragma unroll
                for (int mt = 0; mt < 2; mt++)
#pragma unroll
                    for (int ng2 = 0; ng2 < 4; ng2++) {
                        mma16(acc[mt][ng2 * 2], afr[mt], bfr[ng2][0], bfr[ng2][1]);
                        mma16(acc[mt][ng2 * 2 + 1], afr[mt], bfr[ng2][2], bfr[ng2][3]);
                    }
            }
            if (c + 1 < 64) bar_arrive(5 + s, 384);
        }

        // epilogue: lrelu + store (float2 per pair)
#pragma unroll
        for (int mt = 0; mt < 2; mt++)
#pragma unroll
            for (int rh = 0; rh < 2; rh++) {
                int rloc = wr * 32 + mt * 16 + grp + 8 * rh;
                long grow = (long)b * 2048 + i0 + rloc;
#pragma unroll
                for (int ng = 0; ng < 8; ng++) {
                    int col = wc * 64 + ng * 8 + 2 * tg;
                    float2 vv;
                    vv.x = lrelu(acc[mt][ng][2 * rh]);
                    vv.y = lrelu(acc[mt][ng][2 * rh + 1]);
                    *(float2*)(out + grow * 128 + col) = vv;
                }
            }
    }
}

// ---------------------------------------------------------------------------
extern "C" void kernel_launch(void* const* d_in, const int* in_sizes, int n_in,
                              void* d_out, int out_size) {
    (void)in_sizes; (void)n_in; (void)out_size;
    const float* x   = (const float*)d_in[0];
    const float* adj = (const float*)d_in[1];
    const float* W   = (const float*)d_in[2];
    const float* a   = (const float*)d_in[3];
    float* out = (float*)d_out;

    cudaFuncSetAttribute(k1_h, cudaFuncAttributeMaxDynamicSharedMemorySize,
                         (int)sizeof(SmemK1));
    k1_h<<<256, 256, sizeof(SmemK1)>>>(x, W, a);
    k2_den<<<512, 256>>>();
    cudaFuncSetAttribute(k3_main, cudaFuncAttributeMaxDynamicSharedMemorySize,
                         (int)sizeof(SmemK3));
    k3_main<<<dim3(16, 8), 384, sizeof(SmemK3)>>>(adj, out);
}